// round 8
// baseline (speedup 1.0000x reference)
#include <cuda_runtime.h>
#include <cuda_bf16.h>

// Problem constants (fixed by the reference)
#define BATCH   2
#define NPTS    8192
#define NTOT    (BATCH * NPTS)
#define DIM     32
#define R2      0.0009f     // 0.03^2
#define SIMT    0.7f
#define EPSN    1e-8f
#define MINLEAF 10

#define GRIDC   14                      // ceil(0.4 / 0.03)
#define NCELL   (GRIDC * GRIDC * GRIDC) // 2744
#define CAP     32                      // bucket capacity (mean occupancy ~1.5)
#define INVC    33.333332f              // 1 / 0.03
#define MARGIN  0.0302f                 // radius + safety margin for cell-range bound

#define TPB     256
#define NB      592                     // 148 SMs x 4 blocks: provably co-resident
#define LPP     16                      // lanes per point
#define CH      4                       // points per steal (2 warp-tiles)
#define FULL    0xffffffffu
#define PAD     36                      // smem row pad: 16B-aligned, conflict-safe
#define NSLOT   16                      // 8 warps x 2 groups per block

// Scratch (static __device__ — no allocations allowed)
__device__ float  g_en[NTOT * DIM];                  // normalized embeddings
__device__ int    g_cellcnt[BATCH * NCELL];
__device__ float4 g_bucket[BATCH * NCELL * CAP];     // (x,y,z, bitcast local idx)
__device__ int    g_leafcnt[BATCH];
__device__ int    g_ctr;                             // work-steal counter
__device__ int    g_bar_arrive;                      // zero-initialized
__device__ volatile int g_bar_gen;                   // monotonic epoch (never reset)

// Sense-reversal grid barrier. Safe: launch_bounds(TPB,4) + NB=148*4 and
// smem 40.4KB*4 <= 228KB, regs 64*256*4 = 64K -> all blocks wave-1 resident.
__device__ __forceinline__ void grid_barrier() {
    __syncthreads();
    if (threadIdx.x == 0) {
        int gen = g_bar_gen;
        __threadfence();
        if (atomicAdd(&g_bar_arrive, 1) == NB - 1) {
            atomicExch(&g_bar_arrive, 0);
            __threadfence();
            g_bar_gen = gen + 1;                     // release
        } else {
            while (g_bar_gen == gen) { __nanosleep(20); }
        }
        __threadfence();
    }
    __syncthreads();
}

__global__ void __launch_bounds__(TPB, 4)
fused_kernel(const float* __restrict__ points,
             const float* __restrict__ emb,
             const int*   __restrict__ leaf,
             const float* __restrict__ W1,
             const float* __restrict__ b1,
             const float* __restrict__ W2,
             const float* __restrict__ b2,
             float* __restrict__ out) {
    __shared__ __align__(16) float sW1[2 * DIM * DIM];   // 8 KB
    __shared__ __align__(16) float sW2[DIM * DIM];       // 4 KB
    __shared__ float sb1[DIM];
    __shared__ float sb2[DIM];
    __shared__ int   s_cnt[BATCH * NCELL];               // 21.4 KB (both batches)
    __shared__ __align__(16) float s_en[NSLOT * PAD];    // normalized emb per group slot
    __shared__ __align__(16) float s_ei[NSLOT * PAD];    // raw emb per group slot
    __shared__ float s_acc[NSLOT * PAD];                 // sim-sum accumulators

    const int tid  = threadIdx.x;
    const int gtid = blockIdx.x * TPB + tid;

    // ---- Phase Z: zero grid state ----
    if (gtid < BATCH * NCELL) g_cellcnt[gtid] = 0;
    if (gtid < BATCH)         g_leafcnt[gtid] = 0;
    if (gtid == 0)            g_ctr = 0;
    grid_barrier();

    // ---- Phase P: prep (unchanged numerics; warps fully active or idle) ----
    if (gtid < NTOT) {
        const int idx = gtid;
        const int b = idx / NPTS;
        const int j = idx - b * NPTS;

        const float4* e4 = (const float4*)(emb + (size_t)idx * DIM);
        float v[DIM];
        float s = 0.f;
#pragma unroll
        for (int q = 0; q < 8; q++) {
            float4 t = __ldg(e4 + q);
            v[4*q+0] = t.x; v[4*q+1] = t.y; v[4*q+2] = t.z; v[4*q+3] = t.w;
            s = fmaf(t.x, t.x, s); s = fmaf(t.y, t.y, s);
            s = fmaf(t.z, t.z, s); s = fmaf(t.w, t.w, s);
        }
        float inv = 1.f / fmaxf(sqrtf(s), EPSN);
        float4* o4 = (float4*)(g_en + (size_t)idx * DIM);
#pragma unroll
        for (int q = 0; q < 8; q++)
            o4[q] = make_float4(v[4*q] * inv, v[4*q+1] * inv, v[4*q+2] * inv, v[4*q+3] * inv);

        int lf = leaf[idx] > 0;
        unsigned msk = __ballot_sync(FULL, lf);
        if ((tid & 31) == 0 && msk)
            atomicAdd(&g_leafcnt[b], __popc(msk));

        if (lf) {
            float x = points[3 * (size_t)idx];
            float y = points[3 * (size_t)idx + 1];
            float z = points[3 * (size_t)idx + 2];
            int cx = min(GRIDC - 1, (int)(x * INVC));
            int cy = min(GRIDC - 1, (int)(y * INVC));
            int cz = min(GRIDC - 1, (int)(z * INVC));
            int c = b * NCELL + (cz * GRIDC + cy) * GRIDC + cx;
            int pos = atomicAdd(&g_cellcnt[c], 1);
            if (pos < CAP)
                g_bucket[(size_t)c * CAP + pos] = make_float4(x, y, z, __int_as_float(j));
        }
    }
    grid_barrier();

    // ---- Phase Q: warp-autonomous, work-stolen; NO block syncs in the loop ----
    for (int t = tid; t < 2 * DIM * DIM; t += TPB) sW1[t] = W1[t];
    for (int t = tid; t < DIM * DIM; t += TPB)     sW2[t] = W2[t];
    if (tid < DIM) { sb1[tid] = b1[tid]; sb2[tid] = b2[tid]; }
    for (int t = tid; t < BATCH * NCELL; t += TPB) s_cnt[t] = g_cellcnt[t];
    __syncthreads();                                 // the only block sync in Q

    const int lc0 = g_leafcnt[0], lc1 = g_leafcnt[1];
    const int lane = tid & 31;
    const int ln   = tid & 15;                       // lane within point group
    const int g    = (tid >> 4) & 1;                 // group within warp
    const int slot = (tid >> 5) * 2 + g;             // 0..15 per-block group slot
    const unsigned gmask = 0xFFFFu << (16 * g);      // group's shfl mask
    float* eip  = s_ei  + slot * PAD;
    float* enp  = s_en  + slot * PAD;
    float* accp = s_acc + slot * PAD;

    for (;;) {
        int base = 0;
        if (lane == 0) base = atomicAdd(&g_ctr, CH);
        base = __shfl_sync(FULL, base, 0);
        if (base >= NTOT) break;

        for (int c = 0; c < CH; c += 2) {
            const int gi = base + c + g;             // each group owns one point
            const int b  = gi >> 13;                 // / NPTS

            // stage this point's raw + normalized embedding; zero accumulator
            const float ei_a = __ldg(emb + (size_t)gi * DIM + ln);
            const float ei_b = __ldg(emb + (size_t)gi * DIM + ln + 16);
            eip[ln] = ei_a;                eip[ln + 16] = ei_b;
            enp[ln] = g_en[(size_t)gi * DIM + ln];
            enp[ln + 16] = g_en[(size_t)gi * DIM + ln + 16];
            accp[ln] = 0.f;                accp[ln + 16] = 0.f;
            __syncwarp();

            const float xi = __ldg(points + 3 * (size_t)gi);
            const float yi = __ldg(points + 3 * (size_t)gi + 1);
            const float zi = __ldg(points + 3 * (size_t)gi + 2);

            const int cx0 = max(0, (int)((xi - MARGIN) * INVC)), cx1 = min(GRIDC - 1, (int)((xi + MARGIN) * INVC));
            const int cy0 = max(0, (int)((yi - MARGIN) * INVC)), cy1 = min(GRIDC - 1, (int)((yi + MARGIN) * INVC));
            const int cz0 = max(0, (int)((zi - MARGIN) * INVC)), cz1 = min(GRIDC - 1, (int)((zi + MARGIN) * INVC));
            const int nx = cx1 - cx0 + 1, ny = cy1 - cy0 + 1, nz = cz1 - cz0 + 1;
            const int nxy = nx * ny, ncn = nxy * nz;            // <= 64
            const float invnxy = 1.f / (float)nxy;
            const float invnx  = 1.f / (float)nx;

            int nbcnt = 0, cnt = 0;
            const float* enb  = g_en + (size_t)b * NPTS * DIM;
            const float* embb = emb  + (size_t)b * NPTS * DIM;
            const int*   cntb = s_cnt + b * NCELL;

#pragma unroll
            for (int s = 0; s < 64 / LPP; s++) {                // lane owns cell cc
                int cc = ln + s * LPP;
                if (cc < ncn) {
                    // division-free decode (exact for cc<64)
                    int cz = (int)(((float)cc + 0.5f) * invnxy);
                    int r  = cc - cz * nxy;
                    int cy = (int)(((float)r + 0.5f) * invnx);
                    int cx = r - cy * nx;
                    int cell = ((cz0 + cz) * GRIDC + (cy0 + cy)) * GRIDC + (cx0 + cx);
                    int n = min(cntb[cell], CAP);
                    const float4* bk = g_bucket + ((size_t)b * NCELL + cell) * CAP;
                    for (int k = 0; k < n; k++) {
                        float4 p = __ldg(bk + k);
                        float dx = xi - p.x, dy = yi - p.y, dz = zi - p.z;
                        float d2 = fmaf(dx, dx, fmaf(dy, dy, dz * dz));
                        if (d2 < R2) {
                            nbcnt++;
                            int j = __float_as_int(p.w);
                            const float4* ej = (const float4*)(enb + (size_t)j * DIM);
                            float dot = 0.f;
#pragma unroll
                            for (int q = 0; q < 8; q++) {
                                float4 v = __ldg(ej + q);
                                float4 u = *(const float4*)(enp + 4 * q); // broadcast LDS.128
                                dot = fmaf(v.x, u.x, dot); dot = fmaf(v.y, u.y, dot);
                                dot = fmaf(v.z, u.z, dot); dot = fmaf(v.w, u.w, dot);
                            }
                            if (dot > SIMT) {                   // rare: accumulate RAW embedding
                                cnt++;
                                const float4* rj = (const float4*)(embb + (size_t)j * DIM);
#pragma unroll
                                for (int q = 0; q < 8; q++) {
                                    float4 v = __ldg(rj + q);
                                    atomicAdd(accp + 4*q,     v.x);
                                    atomicAdd(accp + 4*q + 1, v.y);
                                    atomicAdd(accp + 4*q + 2, v.z);
                                    atomicAdd(accp + 4*q + 3, v.w);
                                }
                            }
                        }
                    }
                }
            }

            // 16-lane butterfly reduce (xor d<16 stays within group)
#pragma unroll
            for (int d = 1; d < LPP; d <<= 1) {
                nbcnt += __shfl_xor_sync(FULL, nbcnt, d);
                cnt   += __shfl_xor_sync(FULL, cnt, d);
            }
            __syncwarp();                                       // group smem atomics visible

            const bool cond = (__ldg(leaf + gi) > 0) && (nbcnt > 1) && (cnt > 0)
                           && ((b == 0 ? lc0 : lc1) >= MINLEAF);

            if (cond) {                                         // group-uniform branch
                const float rinv = 1.f / (float)cnt;            // cnt>0 here: == max(cnt,1)
                const int ob = ln * 2;

                float h0 = sb1[ob], h1 = sb1[ob + 1];
#pragma unroll 8
                for (int k = 0; k < DIM; k++) {
                    float cc = eip[k];
                    float2 w = *(const float2*)(sW1 + k * DIM + ob);
                    h0 = fmaf(cc, w.x, h0); h1 = fmaf(cc, w.y, h1);
                }
#pragma unroll 8
                for (int k = 0; k < DIM; k++) {
                    float cc = accp[k] * rinv;
                    float2 w = *(const float2*)(sW1 + (DIM + k) * DIM + ob);
                    h0 = fmaf(cc, w.x, h0); h1 = fmaf(cc, w.y, h1);
                }
                h0 = fmaxf(h0, 0.f); h1 = fmaxf(h1, 0.f);

                // layer 2: h broadcast via width-16 shfl (no smem, no sync)
                float o0 = sb2[ob], o1 = sb2[ob + 1];
#pragma unroll 8
                for (int k16 = 0; k16 < 16; k16++) {
                    float c0 = __shfl_sync(gmask, h0, k16, 16); // h[2*k16]
                    float c1 = __shfl_sync(gmask, h1, k16, 16); // h[2*k16+1]
                    float2 w0 = *(const float2*)(sW2 + (2 * k16) * DIM + ob);
                    o0 = fmaf(c0, w0.x, o0); o1 = fmaf(c0, w0.y, o1);
                    float2 w1 = *(const float2*)(sW2 + (2 * k16 + 1) * DIM + ob);
                    o0 = fmaf(c1, w1.x, o0); o1 = fmaf(c1, w1.y, o1);
                }
                *(float2*)(out + (size_t)gi * DIM + ob) = make_float2(o0, o1);
            } else {
                float2 r = *(const float2*)(eip + 2 * ln);      // passthrough
                *(float2*)(out + (size_t)gi * DIM + 2 * ln) = r;
            }
            __syncwarp();                                       // protect slot reuse
        }
    }
}

extern "C" void kernel_launch(void* const* d_in, const int* in_sizes, int n_in,
                              void* d_out, int out_size) {
    const float* points = (const float*)d_in[0];
    const float* emb    = (const float*)d_in[1];
    const int*   leaf   = (const int*)d_in[2];
    const float* W1     = (const float*)d_in[3];
    const float* b1     = (const float*)d_in[4];
    const float* W2     = (const float*)d_in[5];
    const float* b2     = (const float*)d_in[6];
    float* out = (float*)d_out;

    fused_kernel<<<NB, TPB>>>(points, emb, leaf, W1, b1, W2, b2, out);
}

// round 9
// speedup vs baseline: 1.3222x; 1.3222x over previous
#include <cuda_runtime.h>
#include <cuda_bf16.h>

// Problem constants (fixed by the reference)
#define BATCH   2
#define NPTS    8192
#define NTOT    (BATCH * NPTS)
#define DIM     32
#define R2      0.0009f     // 0.03^2
#define SIMT    0.7f
#define EPSN    1e-8f
#define MINLEAF 10

#define GRIDC   14                      // ceil(0.4 / 0.03)
#define NCELL   (GRIDC * GRIDC * GRIDC) // 2744
#define CAP     32                      // bucket capacity (mean occupancy ~1.5)
#define INVC    33.333332f              // 1 / 0.03
#define MARGIN  0.0302f                 // radius + safety margin for cell-range bound

#define TPB     256
#define NB      512                     // 1024 tiles / 512 blocks = exactly 2 each
#define LPP     16                      // lanes per point
#define PPQ     (TPB / LPP)             // 16 points per tile
#define NTILE   (NTOT / PPQ)            // 1024
#define FULL    0xffffffffu
#define PAD     36                      // smem row pad: 16B-aligned, conflict-safe

// Scratch (static __device__ — no allocations allowed)
__device__ float  g_en[NTOT * DIM];                  // normalized embeddings
__device__ int    g_cellcnt[BATCH * NCELL];
__device__ float4 g_bucket[BATCH * NCELL * CAP];     // (x,y,z, bitcast local idx)
__device__ int    g_leafcnt[BATCH];
__device__ int    g_bar_arrive;                      // zero-initialized
__device__ volatile int g_bar_gen;                   // monotonic epoch (never reset)

// Sense-reversal grid barrier. Safe: NB=512 <= 148 SMs x 4 blocks co-resident
// (regs<=64 via launch_bounds, smem ~41KB*4 <= 228KB).
__device__ __forceinline__ void grid_barrier() {
    __syncthreads();
    if (threadIdx.x == 0) {
        int gen = g_bar_gen;
        __threadfence();
        if (atomicAdd(&g_bar_arrive, 1) == NB - 1) {
            atomicExch(&g_bar_arrive, 0);
            __threadfence();
            g_bar_gen = gen + 1;                     // release
        } else {
            while (g_bar_gen == gen) { __nanosleep(20); }
        }
        __threadfence();
    }
    __syncthreads();
}

__global__ void __launch_bounds__(TPB, 4)
fused_kernel(const float* __restrict__ points,
             const float* __restrict__ emb,
             const int*   __restrict__ leaf,
             const float* __restrict__ W1,
             const float* __restrict__ b1,
             const float* __restrict__ W2,
             const float* __restrict__ b2,
             float* __restrict__ out) {
    __shared__ __align__(16) float sW1[2 * DIM * DIM];   // 8 KB
    __shared__ __align__(16) float sW2[DIM * DIM];       // 4 KB
    __shared__ float sb1[DIM];
    __shared__ float sb2[DIM];
    __shared__ int   s_cnt[BATCH * NCELL];               // 21.4 KB (both batches)
    __shared__ __align__(16) float s_en[PPQ * PAD];      // normalized emb of tile points
    __shared__ __align__(16) float s_ei[PPQ * PAD];      // raw emb of tile points
    __shared__ float s_acc[PPQ * PAD];                   // sim-sum accumulators

    const int tid = threadIdx.x;

    // ---- Phase Z: zero grid state ----
    {
        const int gtid = blockIdx.x * TPB + tid;
        if (gtid < BATCH * NCELL) g_cellcnt[gtid] = 0;
        if (gtid < BATCH)         g_leafcnt[gtid] = 0;
    }
    grid_barrier();

    // ---- Phase P: prep, 32 items per block (16384 = 512*32), 1 item/lane ----
    if (tid < 32) {
        const int idx = blockIdx.x * 32 + tid;           // warp 0 fully active
        const int b = idx / NPTS;                        // warp-homogeneous
        const int j = idx - b * NPTS;

        const float4* e4 = (const float4*)(emb + (size_t)idx * DIM);
        float v[DIM];
        float s = 0.f;
#pragma unroll
        for (int q = 0; q < 8; q++) {
            float4 t = __ldg(e4 + q);
            v[4*q+0] = t.x; v[4*q+1] = t.y; v[4*q+2] = t.z; v[4*q+3] = t.w;
            s = fmaf(t.x, t.x, s); s = fmaf(t.y, t.y, s);
            s = fmaf(t.z, t.z, s); s = fmaf(t.w, t.w, s);
        }
        float inv = 1.f / fmaxf(sqrtf(s), EPSN);
        float4* o4 = (float4*)(g_en + (size_t)idx * DIM);
#pragma unroll
        for (int q = 0; q < 8; q++)
            o4[q] = make_float4(v[4*q] * inv, v[4*q+1] * inv, v[4*q+2] * inv, v[4*q+3] * inv);

        int lf = leaf[idx] > 0;
        unsigned msk = __ballot_sync(FULL, lf);
        if (tid == 0 && msk)
            atomicAdd(&g_leafcnt[b], __popc(msk));

        if (lf) {
            float x = points[3 * (size_t)idx];
            float y = points[3 * (size_t)idx + 1];
            float z = points[3 * (size_t)idx + 2];
            int cx = min(GRIDC - 1, (int)(x * INVC));
            int cy = min(GRIDC - 1, (int)(y * INVC));
            int cz = min(GRIDC - 1, (int)(z * INVC));
            int c = b * NCELL + (cz * GRIDC + cy) * GRIDC + cx;
            int pos = atomicAdd(&g_cellcnt[c], 1);
            if (pos < CAP)
                g_bucket[(size_t)c * CAP + pos] = make_float4(x, y, z, __int_as_float(j));
        }
    }
    grid_barrier();

    // ---- Phase Q: 16 lanes/point, 16 points/tile, exactly 2 tiles/block ----
    for (int t = tid; t < 2 * DIM * DIM; t += TPB) sW1[t] = W1[t];
    for (int t = tid; t < DIM * DIM; t += TPB)     sW2[t] = W2[t];
    if (tid < DIM) { sb1[tid] = b1[tid]; sb2[tid] = b2[tid]; }
    for (int t = tid; t < BATCH * NCELL; t += TPB) s_cnt[t] = g_cellcnt[t];
    __syncthreads();

    const int lc0 = g_leafcnt[0], lc1 = g_leafcnt[1];
    const int pt = tid >> 4;            // 0..15  local point
    const int ln = tid & 15;            // 0..15  lane within point group
    const unsigned gmask = 0xFFFFu << (tid & 16);    // this group's 16 lanes
    const float* en_i = s_en + pt * PAD;
    float* accp = s_acc + pt * PAD;

#pragma unroll
    for (int w = 0; w < 2; w++) {
        const int tile = blockIdx.x + w * NB;
        const int gi0 = tile * PPQ;
        const int b = gi0 >> 13;                         // / NPTS, tile-uniform

        // stage tile embeddings (raw + normalized), zero accumulators
        for (int t = tid; t < PPQ * DIM; t += TPB) {
            int p = t >> 5, k = t & 31;
            s_ei[p * PAD + k]  = __ldg(emb + ((size_t)gi0 + p) * DIM + k);
            s_en[p * PAD + k]  = g_en[((size_t)gi0 + p) * DIM + k];
            s_acc[p * PAD + k] = 0.f;
        }
        __syncthreads();

        const int gi = gi0 + pt;
        const float xi = __ldg(points + 3 * (size_t)gi);
        const float yi = __ldg(points + 3 * (size_t)gi + 1);
        const float zi = __ldg(points + 3 * (size_t)gi + 2);

        const int cx0 = max(0, (int)((xi - MARGIN) * INVC)), cx1 = min(GRIDC - 1, (int)((xi + MARGIN) * INVC));
        const int cy0 = max(0, (int)((yi - MARGIN) * INVC)), cy1 = min(GRIDC - 1, (int)((yi + MARGIN) * INVC));
        const int cz0 = max(0, (int)((zi - MARGIN) * INVC)), cz1 = min(GRIDC - 1, (int)((zi + MARGIN) * INVC));
        const int nx = cx1 - cx0 + 1, ny = cy1 - cy0 + 1, nz = cz1 - cz0 + 1;
        const int nxy = nx * ny, ncn = nxy * nz;         // <= 64
        const float invnxy = 1.f / (float)nxy;
        const float invnx  = 1.f / (float)nx;

        int nbcnt = 0, cnt = 0;
        const float* enb  = g_en + (size_t)b * NPTS * DIM;
        const float* embb = emb  + (size_t)b * NPTS * DIM;
        const int*   cntb = s_cnt + b * NCELL;

#pragma unroll
        for (int s = 0; s < 64 / LPP; s++) {             // 4 iters; lane owns cc
            int cc = ln + s * LPP;
            if (cc < ncn) {
                // division-free decode: exact for cc<64
                int cz = (int)(((float)cc + 0.5f) * invnxy);
                int r  = cc - cz * nxy;
                int cy = (int)(((float)r + 0.5f) * invnx);
                int cx = r - cy * nx;
                int cell = ((cz0 + cz) * GRIDC + (cy0 + cy)) * GRIDC + (cx0 + cx);
                int n = min(cntb[cell], CAP);
                const float4* bk = g_bucket + ((size_t)b * NCELL + cell) * CAP;
                for (int k = 0; k < n; k++) {
                    float4 p = __ldg(bk + k);
                    float dx = xi - p.x, dy = yi - p.y, dz = zi - p.z;
                    float d2 = fmaf(dx, dx, fmaf(dy, dy, dz * dz));
                    if (d2 < R2) {
                        nbcnt++;
                        int j = __float_as_int(p.w);
                        const float4* ej = (const float4*)(enb + (size_t)j * DIM);
                        float dot = 0.f;
#pragma unroll
                        for (int q = 0; q < 8; q++) {
                            float4 v = __ldg(ej + q);
                            float4 u = *(const float4*)(en_i + 4 * q);  // broadcast LDS.128
                            dot = fmaf(v.x, u.x, dot); dot = fmaf(v.y, u.y, dot);
                            dot = fmaf(v.z, u.z, dot); dot = fmaf(v.w, u.w, dot);
                        }
                        if (dot > SIMT) {                // rare: accumulate RAW embedding
                            cnt++;
                            const float4* rj = (const float4*)(embb + (size_t)j * DIM);
#pragma unroll
                            for (int q = 0; q < 8; q++) {
                                float4 v = __ldg(rj + q);
                                atomicAdd(accp + 4*q,     v.x);
                                atomicAdd(accp + 4*q + 1, v.y);
                                atomicAdd(accp + 4*q + 2, v.z);
                                atomicAdd(accp + 4*q + 3, v.w);
                            }
                        }
                    }
                }
            }
        }

        // 16-lane butterfly reduce (xor d<16 stays within group)
#pragma unroll
        for (int d = 1; d < LPP; d <<= 1) {
            nbcnt += __shfl_xor_sync(FULL, nbcnt, d);
            cnt   += __shfl_xor_sync(FULL, cnt, d);
        }
        __syncwarp();                                    // group smem atomics visible

        const bool cond = (__ldg(leaf + gi) > 0) && (nbcnt > 1) && (cnt > 0)
                       && ((b == 0 ? lc0 : lc1) >= MINLEAF);

        const int ob = ln * 2;
        if (cond) {                                      // group-uniform branch
            const float rinv = 1.f / (float)cnt;         // cnt>0 here: == max(cnt,1)

            float h0 = sb1[ob], h1 = sb1[ob + 1];
#pragma unroll 8
            for (int k = 0; k < DIM; k++) {
                float c = s_ei[pt * PAD + k];
                float2 w = *(const float2*)(sW1 + k * DIM + ob);
                h0 = fmaf(c, w.x, h0); h1 = fmaf(c, w.y, h1);
            }
#pragma unroll 8
            for (int k = 0; k < DIM; k++) {
                float c = accp[k] * rinv;
                float2 w = *(const float2*)(sW1 + (DIM + k) * DIM + ob);
                h0 = fmaf(c, w.x, h0); h1 = fmaf(c, w.y, h1);
            }
            h0 = fmaxf(h0, 0.f); h1 = fmaxf(h1, 0.f);

            // layer 2: h broadcast via width-16 shfl (group-converged: cond uniform)
            float o0 = sb2[ob], o1 = sb2[ob + 1];
#pragma unroll 8
            for (int k16 = 0; k16 < 16; k16++) {
                float c0 = __shfl_sync(gmask, h0, k16, 16);   // h[2*k16]
                float c1 = __shfl_sync(gmask, h1, k16, 16);   // h[2*k16+1]
                float2 w0 = *(const float2*)(sW2 + (2 * k16) * DIM + ob);
                o0 = fmaf(c0, w0.x, o0); o1 = fmaf(c0, w0.y, o1);
                float2 w1 = *(const float2*)(sW2 + (2 * k16 + 1) * DIM + ob);
                o0 = fmaf(c1, w1.x, o0); o1 = fmaf(c1, w1.y, o1);
            }
            *(float2*)(out + (size_t)gi * DIM + ob) = make_float2(o0, o1);
        } else {
            float2 r = *(const float2*)(s_ei + pt * PAD + ob);   // passthrough
            *(float2*)(out + (size_t)gi * DIM + ob) = r;
        }
        __syncthreads();                                 // before next tile restage
    }
}

extern "C" void kernel_launch(void* const* d_in, const int* in_sizes, int n_in,
                              void* d_out, int out_size) {
    const float* points = (const float*)d_in[0];
    const float* emb    = (const float*)d_in[1];
    const int*   leaf   = (const int*)d_in[2];
    const float* W1     = (const float*)d_in[3];
    const float* b1     = (const float*)d_in[4];
    const float* W2     = (const float*)d_in[5];
    const float* b2     = (const float*)d_in[6];
    float* out = (float*)d_out;

    fused_kernel<<<NB, TPB>>>(points, emb, leaf, W1, b1, W2, b2, out);
}